// round 16
// baseline (speedup 1.0000x reference)
#include <cuda_runtime.h>
#include <cuda_fp16.h>
#include <math_constants.h>
#include <cstdint>

#define N_EMBED 1024
#define HEAD    64
#define BATCH   8
#define SEQ     2048
#define MROWS   (BATCH * SEQ)   // 16384

// ---------------------------------------------------------------------------
// Global scratch (fp16)
// ---------------------------------------------------------------------------
__device__ uint16_t g_qh[MROWS * HEAD];                            // Q*0.125*log2e fp16
__device__ uint16_t g_kh[MROWS * HEAD];                            // K fp16 [row][head]
__device__ uint16_t g_vth[MROWS * HEAD];                           // V^T fp16 [b][head][seq]
__device__ uint16_t g_wth[3 * HEAD * N_EMBED];                     // W^T fp16 [which][n][k]
// split-KV partials (4 slots per tile) + completion counters
__device__ float g_po[BATCH * 32 * 4 * 64 * 64];
__device__ float g_pm[BATCH * 32 * 4 * 64];
__device__ float g_pl[BATCH * 32 * 4 * 64];
__device__ int   g_cnt[BATCH * 32];     // zero-init; +n per replay per split tile

// ---------------------------------------------------------------------------
// helpers
// ---------------------------------------------------------------------------
__device__ __forceinline__ uint32_t packhf(float x0, float x1) {
    __half2 h = __floats2half2_rn(x0, x1);
    return *reinterpret_cast<uint32_t*>(&h);
}
__device__ __forceinline__ float ex2f(float x) {
    float y;
    asm("ex2.approx.f32 %0, %1;" : "=f"(y) : "f"(x));
    return y;
}
__device__ __forceinline__ void mma16(float4& c,
                                      uint32_t a0, uint32_t a1, uint32_t a2, uint32_t a3,
                                      uint32_t b0, uint32_t b1) {
    asm volatile(
        "mma.sync.aligned.m16n8k16.row.col.f32.f16.f16.f32 "
        "{%0,%1,%2,%3}, {%4,%5,%6,%7}, {%8,%9}, {%0,%1,%2,%3};"
        : "+f"(c.x), "+f"(c.y), "+f"(c.z), "+f"(c.w)
        : "r"(a0), "r"(a1), "r"(a2), "r"(a3), "r"(b0), "r"(b1));
}
__device__ __forceinline__ void ldsm4(uint32_t& r0, uint32_t& r1, uint32_t& r2,
                                      uint32_t& r3, uint32_t addr) {
    asm volatile("ldmatrix.sync.aligned.m8n8.x4.shared.b16 {%0,%1,%2,%3}, [%4];"
                 : "=r"(r0), "=r"(r1), "=r"(r2), "=r"(r3) : "r"(addr));
}
__device__ __forceinline__ void cp16(uint32_t dst, const void* src) {
    asm volatile("cp.async.cg.shared.global [%0], [%1], 16;" :: "r"(dst), "l"(src));
}
__device__ __forceinline__ void cp_commit() {
    asm volatile("cp.async.commit_group;");
}
template <int N>
__device__ __forceinline__ void cp_wait() {
    asm volatile("cp.async.wait_group %0;" :: "n"(N));
}
__device__ __forceinline__ uint32_t smem_u32(const void* p) {
    return (uint32_t)__cvta_generic_to_shared(p);
}

// 0.125 * log2(e): folded into Q so softmax uses exp2 directly
#define QSCALE 0.18033688011112042f

// ---------------------------------------------------------------------------
// wprep: W [k][n] fp32 -> W^T [n][k] fp16.  grid (64, 3), 256 thr.
// ---------------------------------------------------------------------------
__global__ __launch_bounds__(256) void wprep_kernel(
    const float* __restrict__ Wq, const float* __restrict__ Wk,
    const float* __restrict__ Wv)
{
    const int which = blockIdx.y;
    const float* __restrict__ W = (which == 0) ? Wq : (which == 1) ? Wk : Wv;
    const int k0 = blockIdx.x * 16;

    __shared__ float sw[16][68];
    const int t = threadIdx.x;
    {
        const int r = t >> 4, c4 = (t & 15) * 4;
        float4 v = *reinterpret_cast<const float4*>(&W[(size_t)(k0 + r) * HEAD + c4]);
        sw[r][c4 + 0] = v.x; sw[r][c4 + 1] = v.y;
        sw[r][c4 + 2] = v.z; sw[r][c4 + 3] = v.w;
    }
    __syncthreads();
    {
        const int n = t >> 2, kg = (t & 3) * 4;
        uint32_t h0 = packhf(sw[kg + 0][n], sw[kg + 1][n]);
        uint32_t h1 = packhf(sw[kg + 2][n], sw[kg + 3][n]);
        size_t off = ((size_t)(which * HEAD + n)) * N_EMBED + k0 + kg;
        *reinterpret_cast<uint2*>(&g_wth[off]) = make_uint2(h0, h1);
    }
}

// ---------------------------------------------------------------------------
// Fused proj v3: 64-row M-tiles, 256 CTAs, K-chunk 32 (32 chunks).
// x staged fp32 via cp.async (2 slots, pitch 36) -> converted to fp16 tile.
// W fp16 staged via cp.async into 3-slot ring (race-free).
// smem 69632 B -> 3 CTA/SM; all SMs covered, deep latency hiding.
// ---------------------------------------------------------------------------
#define PXF    36                        // fp32 pitch (floats)
#define PXFSZ  (64 * PXF * 4)            // 9216 B per slot
#define PXH    40                        // fp16 pitch (halves)
#define PXH_OFF (2 * PXFSZ)              // 18432
#define PXHSZ  (64 * PXH * 2)            // 5120 B
#define PW_OFF (PXH_OFF + PXHSZ)         // 23552
#define PWTSZ  (64 * PXH * 2)            // 5120 B per which-tile
#define PWOFF(ring, w) (PW_OFF + ((ring) * 3 + (w)) * PWTSZ)
#define PROJ_SMEM (PW_OFF + 9 * PWTSZ)   // 69632 B

__device__ __forceinline__ void proj_stage(char* sm, const float* __restrict__ x,
                                           int m0, int ch, int t)
{
    const int kc0 = ch * 32;
    // x fp32: 64 rows x 8 float4 = 512 blocks (2 per thread)
    #pragma unroll
    for (int i = 0; i < 2; i++) {
        int u = t + i * 256;
        int row = u >> 3, q = u & 7;
        const float* src = x + (size_t)(m0 + row) * N_EMBED + kc0 + q * 4;
        uint32_t d = smem_u32(sm + (ch & 1) * PXFSZ + (row * PXF + q * 4) * 4);
        cp16(d, src);
    }
    // W fp16: 3 which x 64 rows x 4 blocks = 768 blocks (3 per thread)
    #pragma unroll
    for (int i = 0; i < 3; i++) {
        int u = t + i * 256;
        int w = u >> 8, rem = u & 255;
        int row = rem >> 2, q = rem & 3;
        const uint16_t* src = g_wth + (size_t)(w * HEAD + row) * N_EMBED + kc0 + q * 8;
        uint32_t d = smem_u32(sm + PWOFF(ch % 3, w) + (row * PXH + q * 8) * 2);
        cp16(d, src);
    }
    cp_commit();
}

__global__ __launch_bounds__(256) void proj_kernel(const float* __restrict__ x)
{
    extern __shared__ char sm[];
    const int m0 = blockIdx.x * 64;
    const int t = threadIdx.x;
    const int warp = t >> 5, lane = t & 31;
    const int g = lane >> 2, tg = lane & 3;
    const int wm = warp >> 1, wn = warp & 1;
    const int l8 = lane & 7, mi = lane >> 3;

    const uint32_t smu = smem_u32(sm);
    const uint32_t aX = smu + PXH_OFF +
        ((wm * 16 + ((mi & 1) << 3) + l8) * PXH + ((mi >> 1) << 3)) * 2;
    const uint32_t bWl =
        ((uint32_t)(wn * 32 + ((mi >> 1) << 3) + l8) * PXH + ((mi & 1) << 3)) * 2;

    float4 acc[3][4] = {};

    proj_stage(sm, x, m0, 0, t);
    proj_stage(sm, x, m0, 1, t);

    const int cr = t >> 2, cc = (t & 3) * 8;   // convert mapping: row, 8 cols

    for (int ch = 0; ch < 32; ch++) {
        if (ch == 31) cp_wait<0>(); else cp_wait<1>();
        __syncthreads();           // chunk ch staged; all warps past prior MMA

        // convert x fp32 -> fp16 tile
        {
            const float* xf = reinterpret_cast<const float*>(sm + (ch & 1) * PXFSZ) +
                              cr * PXF + cc;
            float4 f0 = *reinterpret_cast<const float4*>(xf);
            float4 f1 = *reinterpret_cast<const float4*>(xf + 4);
            uint16_t* dst = reinterpret_cast<uint16_t*>(sm + PXH_OFF) + cr * PXH + cc;
            *reinterpret_cast<uint4*>(dst) =
                make_uint4(packhf(f0.x, f0.y), packhf(f0.z, f0.w),
                           packhf(f1.x, f1.y), packhf(f1.z, f1.w));
        }
        __syncthreads();           // fp16 tile ready; fp32 slot (ch&1) free

        if (ch + 2 < 32) proj_stage(sm, x, m0, ch + 2, t);

        const int ring = ch % 3;
        #pragma unroll
        for (int kk = 0; kk < 2; kk++) {
            uint32_t a0[4];
            ldsm4(a0[0], a0[1], a0[2], a0[3], aX + kk * 32);
            #pragma unroll
            for (int w = 0; w < 3; w++) {
                const uint32_t bw = smu + PWOFF(ring, w) + bWl;
                #pragma unroll
                for (int ntp = 0; ntp < 2; ntp++) {
                    uint32_t ba = bw + ntp * (16 * PXH * 2) + kk * 32;
                    uint32_t b0, b1, b2, b3;
                    ldsm4(b0, b1, b2, b3, ba);
                    mma16(acc[w][2*ntp],   a0[0], a0[1], a0[2], a0[3], b0, b1);
                    mma16(acc[w][2*ntp+1], a0[0], a0[1], a0[2], a0[3], b2, b3);
                }
            }
        }
        // no trailing sync: next iteration's top sync orders MMA before convert
    }
    __syncthreads();   // all MMA done before smem reuse

    // ---- epilogue: Q scaled fp16; K plain fp16 ----
    #pragma unroll
    for (int nt = 0; nt < 4; nt++) {
        int m   = m0 + wm * 16 + g;
        int col = wn * 32 + nt * 8 + 2 * tg;
        reinterpret_cast<uint32_t*>(g_qh)[((size_t)m * HEAD + col) >> 1] =
            packhf(acc[0][nt].x * QSCALE, acc[0][nt].y * QSCALE);
        reinterpret_cast<uint32_t*>(g_qh)[((size_t)(m + 8) * HEAD + col) >> 1] =
            packhf(acc[0][nt].z * QSCALE, acc[0][nt].w * QSCALE);
        reinterpret_cast<uint32_t*>(g_kh)[((size_t)m * HEAD + col) >> 1] =
            packhf(acc[1][nt].x, acc[1][nt].y);
        reinterpret_cast<uint32_t*>(g_kh)[((size_t)(m + 8) * HEAD + col) >> 1] =
            packhf(acc[1][nt].z, acc[1][nt].w);
    }

    // ---- epilogue: V -> V^T fp16 (fused transpose via smem) ----
    float* sv = reinterpret_cast<float*>(sm);   // [64][68] fp32 = 17408 B
    #pragma unroll
    for (int nt = 0; nt < 4; nt++) {
        int r0 = wm * 16 + g;
        int col = wn * 32 + nt * 8 + 2 * tg;
        sv[r0 * 68 + col] = acc[2][nt].x; sv[r0 * 68 + col + 1] = acc[2][nt].y;
        sv[(r0 + 8) * 68 + col] = acc[2][nt].z; sv[(r0 + 8) * 68 + col + 1] = acc[2][nt].w;
    }
    __syncthreads();
    {
        const int r = t >> 2, c16 = (t & 3) * 16;
        uint32_t hp[8];
        #pragma unroll
        for (int i = 0; i < 8; i++)
            hp[i] = packhf(sv[(c16 + 2 * i) * 68 + r], sv[(c16 + 2 * i + 1) * 68 + r]);
        const int b = m0 >> 11;
        const int seq0 = m0 & 2047;
        size_t off = ((size_t)(b * HEAD + r)) * SEQ + seq0 + c16;
        *reinterpret_cast<uint4*>(&g_vth[off    ]) = make_uint4(hp[0], hp[1], hp[2], hp[3]);
        *reinterpret_cast<uint4*>(&g_vth[off + 8]) = make_uint4(hp[4], hp[5], hp[6], hp[7]);
    }
}

// ---------------------------------------------------------------------------
// attn: split-KV depth 8, up to 4 slots per tile, n-way inline merge
// (unchanged from R15). grid (80, 8), 128 thr, smem 6 tiles = 55296 B.
// ---------------------------------------------------------------------------
#define APE 72
#define APB (64 * APE * 2)
#define ATTN_SMEM (6 * APB)              // 55296 bytes

__constant__ uchar4 c_units[80] = {
    {31,0,8,0},{31,8,16,1},{31,16,24,2},{31,24,32,3},
    {30,0,8,0},{30,8,16,1},{30,16,24,2},
    {29,0,8,0},{29,8,16,1},{29,16,24,2},
    {28,0,8,0},{28,8,16,1},{28,16,24,2},
    {27,0,8,0},{27,8,16,1},{27,16,24,2},
    {26,0,8,0},{26,8,16,1},{26,16,24,2},
    {25,0,8,0},{25,8,16,1},{25,16,24,2},
    {24,0,8,0},{24,8,16,1},{24,16,24,2},
    {23,0,8,0},{23,8,16,1},{23,16,24,2},
    {22,0,8,0},{22,8,16,1},
    {21,0,8,0},{21,8,16,1},
    {20,0,8,0},{20,8,16,1},
    {19,0,8,0},{19,8,16,1},
    {18,0,8,0},{18,8,16,1},
    {17,0,8,0},{17,8,16,1},
    {16,0,8,0},{16,8,16,1},
    {15,0,8,0},{15,8,16,1},
    {14,0,8,0},{13,0,8,0},{12,0,8,0},{11,0,8,0},
    {10,0,8,0},{9,0,8,0},{8,0,8,0},{7,0,8,0},
    {30,24,31,3},{22,16,23,2},{14,8,15,1},{6,0,7,0},
    {29,24,30,3},{21,16,22,2},{13,8,14,1},{5,0,6,0},
    {28,24,29,3},{20,16,21,2},{12,8,13,1},{4,0,5,0},
    {27,24,28,3},{19,16,20,2},{11,8,12,1},{3,0,4,0},
    {26,24,27,3},{18,16,19,2},{10,8,11,1},{2,0,3,0},
    {25,24,26,3},{17,16,18,2},{9,8,10,1},{1,0,2,0},
    {24,24,25,3},{16,16,17,2},{8,8,9,1},{0,0,1,0}
};

__device__ __forceinline__ void stage_kv(char* sm,
    const uint16_t* __restrict__ gk, const uint16_t* __restrict__ gv,
    int j, int tid)
{
    char* smbuf = sm + 2 * (j % 3) * APB;
    #pragma unroll
    for (int i = 0; i < 4; i++) {
        int u = tid + i * 128;
        int r = u >> 3, c8 = (u & 7) * 8;
        uint32_t d = smem_u32(smbuf + (r * APE + c8) * 2);
        cp16(d,       gk + (size_t)(j * 64 + r) * HEAD + c8);
        cp16(d + APB, gv + (size_t)r * SEQ + j * 64 + c8);
    }
    cp_commit();
}

__global__ __launch_bounds__(128, 4) void attn_kernel(float* __restrict__ out)
{
    extern __shared__ char sm[];
    __shared__ int s_flag;
    const uchar4 u = c_units[blockIdx.x];
    const int tile = u.x, c0 = u.y, c1 = u.z, slot = u.w;
    const int b = blockIdx.y;
    const int tid = threadIdx.x;
    const int warp = tid >> 5, lane = tid & 31;
    const int g = lane >> 2, tg = lane & 3;
    const int qr = warp * 16;
    const int l8 = lane & 7, mi = lane >> 3;

    const uint32_t smu = smem_u32(sm);
    const uint32_t bloc = ((((mi >> 1) << 3) + l8) * APE + ((mi & 1) << 3)) * 2;

    const int qslot = (c0 + 2) % 3;
    uint16_t* qh = reinterpret_cast<uint16_t*>(sm + 2 * qslot * APB);
    const uint32_t aQ = smu + 2 * qslot * APB +
        ((qr + ((mi & 1) << 3) + l8) * APE + ((mi >> 1) << 3)) * 2;

    const uint16_t* __restrict__ gqh = g_qh + (size_t)b * SEQ * HEAD;
    const uint16_t* __restrict__ gkh = g_kh + (size_t)b * SEQ * HEAD;
    const uint16_t* __restrict__ gvh = g_vth + (size_t)b * HEAD * SEQ;

    stage_kv(sm, gkh, gvh, c0, tid);
    if (c0 + 1 < c1) stage_kv(sm, gkh, gvh, c0 + 1, tid);

    #pragma unroll
    for (int i = 0; i < 4; i++) {
        int uu = tid + i * 128;
        int r = uu >> 3, c8 = (uu & 7) * 8;
        *reinterpret_cast<uint4*>(&qh[r * APE + c8]) =
            *reinterpret_cast<const uint4*>(&gqh[(size_t)(tile * 64 + r) * HEAD + c8]);
    }
    __syncthreads();

    uint32_t aq[4][4];
    #pragma unroll
    for (int kk = 0; kk < 4; kk++)
        ldsm4(aq[kk][0], aq[kk][1], aq[kk][2], aq[kk][3], aQ + kk * 32);

    float mx0 = -CUDART_INF_F, mx1 = -CUDART_INF_F;
    float l0 = 0.f, l1 = 0.f;
    float4 o[8] = {};

    for (int j = c0; j < c1; j++) {
        if (j == c1 - 1) cp_wait<0>(); else cp_wait<1>();
        __syncthreads();

        if (j + 2 < c1) stage_kv(sm, gkh, gvh, j + 2, tid);

        const uint32_t kb = smu + 2 * (j % 3) * APB + bloc;
        const uint32_t vb = kb + APB;

        float4 s[8] = {};
        #pragma unroll
        for (int kk = 0; kk < 4; kk++) {
            #pragma unroll
            for (int ntp = 0; ntp < 4; ntp++) {
                uint32_t ba = kb + ntp * (16 * APE * 2) + kk * 32;
                uint32_t bh0, bh1, bh2, bh3;
                ldsm4(bh0, bh1, bh2, bh3, ba);
                mma16(s[2*ntp],   aq[kk][0], aq[kk][1], aq[kk][2], aq[kk][3], bh0, bh1);
                mma16(s[2*ntp+1], aq[kk][0], aq[kk][1], aq[kk][2], aq[kk][3], bh2, bh3);
            }
        }

        if (j == tile) {
            const int rg0 = tile * 64 + qr + g;
            const int rg1 = rg0 + 8;
            #pragma unroll
            for (int nt = 0; nt < 8; nt++) {
                const int cg = j * 64 + nt * 8 + 2 * tg;
                if (cg     > rg0) s[nt].x = -CUDART_INF_F;
                if (cg + 1 > rg0) s[nt].y = -CUDART_INF_F;
                if (cg     > rg1) s[nt].z = -CUDART_INF_F;
                if (cg + 1 > rg1) s[nt].w = -CUDART_INF_F;
            }
        }

        float rm0 = -CUDART_INF_F, rm1 = -CUDART_INF_F;
        #pragma unroll
        for (int nt = 0; nt < 8; nt++) {
            rm0 = fmaxf(rm0, fmaxf(s[nt].x, s[nt].y));
            rm1 = fmaxf(rm1, fmaxf(s[nt].z, s[nt].w));
        }
        rm0 = fmaxf(rm0, __shfl_xor_sync(0xffffffffu, rm0, 1));
        rm0 = fmaxf(rm0, __shfl_xor_sync(0xffffffffu, rm0, 2));
        rm1 = fmaxf(rm1, __shfl_xor_sync(0xffffffffu, rm1, 1));
        rm1 = fmaxf(rm1, __shfl_xor_sync(0xffffffffu, rm1, 2));

        const bool renorm = __any_sync(0xffffffffu, (rm0 > mx0) | (rm1 > mx1));
        if (renorm) {
            const float nm0 = fmaxf(mx0, rm0);
            const float nm1 = fmaxf(mx1, rm1);
            const float a0 = ex2f(mx0 - nm0);
            const float a1 = ex2f(mx1 - nm1);
            l0 *= a0; l1 *= a1;
            mx0 = nm0; mx1 = nm1;
            #pragma unroll
            for (int nt = 0; nt < 8; nt++) {
                o[nt].x *= a0; o[nt].y *= a0;
                o[nt].z *= a1; o[nt].w *= a1;
            }
        }

        uint32_t pa[8], pb[8];
        float rs0 = 0.f, rs1 = 0.f;
        #pragma unroll
        for (int nt = 0; nt < 8; nt++) {
            float px = ex2f(s[nt].x - mx0);
            float py = ex2f(s[nt].y - mx0);
            float pz = ex2f(s[nt].z - mx1);
            float pw = ex2f(s[nt].w - mx1);
            rs0 += px + py;
            rs1 += pz + pw;
            pa[nt] = packhf(px, py);
            pb[nt] = packhf(pz, pw);
        }
        l0 += rs0;
        l1 += rs1;

        #pragma unroll
        for (int kk = 0; kk < 4; kk++) {
            uint32_t a0f = pa[2 * kk],     a1f = pb[2 * kk];
            uint32_t a2f = pa[2 * kk + 1], a3f = pb[2 * kk + 1];
            #pragma unroll
            for (int ntp = 0; ntp < 4; ntp++) {
                uint32_t ba = vb + ntp * (16 * APE * 2) + kk * 32;
                uint32_t vh0, vh1, vh2, vh3;
                ldsm4(vh0, vh1, vh2, vh3, ba);
                mma16(o[2*ntp],   a0f, a1f, a2f, a3f, vh0, vh1);
                mma16(o[2*ntp+1], a0f, a1f, a2f, a3f, vh2, vh3);
            }
        }
    }

    l0 += __shfl_xor_sync(0xffffffffu, l0, 1);
    l0 += __shfl_xor_sync(0xffffffffu, l0, 2);
    l1 += __shfl_xor_sync(0xffffffffu, l1, 1);
    l1 += __shfl_xor_sync(0xffffffffu, l1, 2);

    const int n = (tile >> 3) + 1;

    if (n == 1) {
        const float inv0 = __frcp_rn(l0);
        const float inv1 = __frcp_rn(l1);
        #pragma unroll
        for (int nt = 0; nt < 8; nt++) {
            int col = nt * 8 + 2 * tg;
            *reinterpret_cast<float2*>(
                &out[((size_t)b * SEQ + tile * 64 + qr + g    ) * HEAD + col]) =
                make_float2(o[nt].x * inv0, o[nt].y * inv0);
            *reinterpret_cast<float2*>(
                &out[((size_t)b * SEQ + tile * 64 + qr + g + 8) * HEAD + col]) =
                make_float2(o[nt].z * inv1, o[nt].w * inv1);
        }
        return;
    }

    const int tix  = b * 32 + tile;
    const int sidx = tix * 4 + slot;
    {
        float* po = g_po + (size_t)sidx * 64 * 64;
        #pragma unroll
        for (int nt = 0; nt < 8; nt++) {
            int col = nt * 8 + 2 * tg;
            *reinterpret_cast<float2*>(&po[(qr + g    ) * 64 + col]) = make_float2(o[nt].x, o[nt].y);
            *reinterpret_cast<float2*>(&po[(qr + g + 8) * 64 + col]) = make_float2(o[nt].z, o[nt].w);
        }
        if (tg == 0) {
            g_pm[sidx * 64 + qr + g    ] = mx0;
            g_pm[sidx * 64 + qr + g + 8] = mx1;
            g_pl[sidx * 64 + qr + g    ] = l0;
            g_pl[sidx * 64 + qr + g + 8] = l1;
        }
    }
    __threadfence();
    __syncthreads();
    if (tid == 0) {
        int old = atomicAdd(&g_cnt[tix], 1);
        s_flag = ((old % n) == (n - 1));
    }
    __syncthreads();
    if (!s_flag) return;
    __threadfence();

    const int r0i = qr + g, r1i = qr + g + 8;
    float pm0[4], pm1[4], pL0[4], pL1[4];
    float m0f = -CUDART_INF_F, m1f = -CUDART_INF_F;
    for (int sN = 0; sN < n; sN++) {
        pm0[sN] = g_pm[(tix * 4 + sN) * 64 + r0i];
        pm1[sN] = g_pm[(tix * 4 + sN) * 64 + r1i];
        pL0[sN] = g_pl[(tix * 4 + sN) * 64 + r0i];
        pL1[sN] = g_pl[(tix * 4 + sN) * 64 + r1i];
        m0f = fmaxf(m0f, pm0[sN]);
        m1f = fmaxf(m1f, pm1[sN]);
    }
    float w0[4], w1[4], L0 = 0.f, L1 = 0.f;
    for (int sN = 0; sN < n; sN++) {
        w0[sN] = ex2f(pm0[sN] - m0f);
        w1[sN] = ex2f(pm1[sN] - m1f);
        L0 += w0[sN] * pL0[sN];
        L1 += w1[sN] * pL1[sN];
    }
    const float inv0 = __frcp_rn(L0);
    const float inv1 = __frcp_rn(L1);
    for (int sN = 0; sN < n; sN++) { w0[sN] *= inv0; w1[sN] *= inv1; }

    #pragma unroll
    for (int nt = 0; nt < 8; nt++) {
        int col = nt * 8 + 2 * tg;
        float2 acc0 = make_float2(0.f, 0.f), acc1 = make_float2(0.f, 0.f);
        for (int sN = 0; sN < n; sN++) {
            const float* pp = g_po + (size_t)(tix * 4 + sN) * 64 * 64;
            float2 v0 = *reinterpret_cast<const float2*>(&pp[r0i * 64 + col]);
            float2 v1 = *reinterpret_cast<const float2*>(&pp[r1i * 64 + col]);
            acc0.x += v0.x * w0[sN]; acc0.y += v0.y * w0[sN];
            acc1.x += v1.x * w1[sN]; acc1.y += v1.y * w1[sN];
        }
        *reinterpret_cast<float2*>(
            &out[((size_t)b * SEQ + tile * 64 + r0i) * HEAD + col]) = acc0;
        *reinterpret_cast<float2*>(
            &out[((size_t)b * SEQ + tile * 64 + r1i) * HEAD + col]) = acc1;
    }
}

// ---------------------------------------------------------------------------
extern "C" void kernel_launch(void* const* d_in, const int* in_sizes, int n_in,
                              void* d_out, int out_size)
{
    const float* x  = (const float*)d_in[0];
    const float* Wq = (const float*)d_in[1];
    const float* Wk = (const float*)d_in[2];
    const float* Wv = (const float*)d_in[3];
    float* out = (float*)d_out;

    (void)in_sizes; (void)n_in; (void)out_size;

    cudaFuncSetAttribute(proj_kernel,
                         cudaFuncAttributeMaxDynamicSharedMemorySize, PROJ_SMEM);
    cudaFuncSetAttribute(attn_kernel,
                         cudaFuncAttributeMaxDynamicSharedMemorySize, ATTN_SMEM);

    wprep_kernel<<<dim3(64, 3), 256>>>(Wq, Wk, Wv);
    proj_kernel<<<256, 256, PROJ_SMEM>>>(x);
    attn_kernel<<<dim3(80, 8), 128, ATTN_SMEM>>>(out);
}

// round 17
// speedup vs baseline: 1.0343x; 1.0343x over previous
#include <cuda_runtime.h>
#include <cuda_fp16.h>
#include <math_constants.h>
#include <cstdint>

#define N_EMBED 1024
#define HEAD    64
#define BATCH   8
#define SEQ     2048
#define MROWS   (BATCH * SEQ)   // 16384

// ---------------------------------------------------------------------------
// Global scratch (fp16)
// ---------------------------------------------------------------------------
__device__ uint16_t g_qh[MROWS * HEAD];                            // Q*0.125*log2e fp16
__device__ uint16_t g_kh[MROWS * HEAD];                            // K fp16 [row][head]
__device__ uint16_t g_vth[MROWS * HEAD];                           // V^T fp16 [b][head][seq]
__device__ uint16_t g_wth[3 * HEAD * N_EMBED];                     // W^T fp16 [which][n][k]
// split-KV partials (4 slots per tile) + completion counters
__device__ float g_po[BATCH * 32 * 4 * 64 * 64];
__device__ float g_pm[BATCH * 32 * 4 * 64];
__device__ float g_pl[BATCH * 32 * 4 * 64];
__device__ int   g_cnt[BATCH * 32];     // zero-init; +n per replay per split tile

// ---------------------------------------------------------------------------
// helpers
// ---------------------------------------------------------------------------
__device__ __forceinline__ uint32_t packhf(float x0, float x1) {
    __half2 h = __floats2half2_rn(x0, x1);
    return *reinterpret_cast<uint32_t*>(&h);
}
__device__ __forceinline__ float ex2f(float x) {
    float y;
    asm("ex2.approx.f32 %0, %1;" : "=f"(y) : "f"(x));
    return y;
}
__device__ __forceinline__ void mma16(float4& c,
                                      uint32_t a0, uint32_t a1, uint32_t a2, uint32_t a3,
                                      uint32_t b0, uint32_t b1) {
    asm volatile(
        "mma.sync.aligned.m16n8k16.row.col.f32.f16.f16.f32 "
        "{%0,%1,%2,%3}, {%4,%5,%6,%7}, {%8,%9}, {%0,%1,%2,%3};"
        : "+f"(c.x), "+f"(c.y), "+f"(c.z), "+f"(c.w)
        : "r"(a0), "r"(a1), "r"(a2), "r"(a3), "r"(b0), "r"(b1));
}
__device__ __forceinline__ void ldsm4(uint32_t& r0, uint32_t& r1, uint32_t& r2,
                                      uint32_t& r3, uint32_t addr) {
    asm volatile("ldmatrix.sync.aligned.m8n8.x4.shared.b16 {%0,%1,%2,%3}, [%4];"
                 : "=r"(r0), "=r"(r1), "=r"(r2), "=r"(r3) : "r"(addr));
}
__device__ __forceinline__ void cp16(uint32_t dst, const void* src) {
    asm volatile("cp.async.cg.shared.global [%0], [%1], 16;" :: "r"(dst), "l"(src));
}
__device__ __forceinline__ void cp_commit() {
    asm volatile("cp.async.commit_group;");
}
template <int N>
__device__ __forceinline__ void cp_wait() {
    asm volatile("cp.async.wait_group %0;" :: "n"(N));
}
__device__ __forceinline__ uint32_t smem_u32(const void* p) {
    return (uint32_t)__cvta_generic_to_shared(p);
}

// 0.125 * log2(e): folded into Q so softmax uses exp2 directly
#define QSCALE 0.18033688011112042f

// ---------------------------------------------------------------------------
// wprep: W [k][n] fp32 -> W^T [n][k] fp16.  grid (64, 3), 256 thr.
// ---------------------------------------------------------------------------
__global__ __launch_bounds__(256) void wprep_kernel(
    const float* __restrict__ Wq, const float* __restrict__ Wk,
    const float* __restrict__ Wv)
{
    const int which = blockIdx.y;
    const float* __restrict__ W = (which == 0) ? Wq : (which == 1) ? Wk : Wv;
    const int k0 = blockIdx.x * 16;

    __shared__ float sw[16][68];
    const int t = threadIdx.x;
    {
        const int r = t >> 4, c4 = (t & 15) * 4;
        float4 v = *reinterpret_cast<const float4*>(&W[(size_t)(k0 + r) * HEAD + c4]);
        sw[r][c4 + 0] = v.x; sw[r][c4 + 1] = v.y;
        sw[r][c4 + 2] = v.z; sw[r][c4 + 3] = v.w;
    }
    __syncthreads();
    {
        const int n = t >> 2, kg = (t & 3) * 4;
        uint32_t h0 = packhf(sw[kg + 0][n], sw[kg + 1][n]);
        uint32_t h1 = packhf(sw[kg + 2][n], sw[kg + 3][n]);
        size_t off = ((size_t)(which * HEAD + n)) * N_EMBED + k0 + kg;
        *reinterpret_cast<uint2*>(&g_wth[off]) = make_uint2(h0, h1);
    }
}

// ---------------------------------------------------------------------------
// Fused proj v2 + PDL: 128-row M-tiles, 128 CTAs, K-chunk 64 (16 chunks).
// x staging (independent of wprep) issues BEFORE the grid-dependency sync;
// W staging waits for wprep via cudaGridDependencySynchronize().
// ---------------------------------------------------------------------------
#define XFP    68
#define XFSZ   (128 * XFP * 4)
#define XF(buf) ((buf) * XFSZ)
#define WPH    72
#define XHOFF  (2 * XFSZ)
#define WBASE  (XHOFF + 128 * WPH * 2)
#define WTSZ   (64 * WPH * 2)
#define WOFF(ring, w) (WBASE + ((ring) * 3 + (w)) * WTSZ)
#define PROJ_SMEM (WBASE + 9 * WTSZ)

__device__ __forceinline__ void proj_stage_x(char* sm, const float* __restrict__ x,
                                             int m0, int ch, int t)
{
    const int kc0 = ch * 64;
    #pragma unroll
    for (int i = 0; i < 8; i++) {
        int u = t + i * 256;
        int row = u >> 4, q = u & 15;
        const float* src = x + (size_t)(m0 + row) * N_EMBED + kc0 + q * 4;
        uint32_t d = smem_u32(sm + XF(ch & 1) + (row * XFP + q * 4) * 4);
        cp16(d, src);
    }
}

__device__ __forceinline__ void proj_stage_w(char* sm, int ch, int t)
{
    const int kc0 = ch * 64;
    #pragma unroll
    for (int i = 0; i < 6; i++) {
        int u = t + i * 256;
        int w = u >> 9, rem = u & 511;
        int row = rem >> 3, q = rem & 7;
        const uint16_t* src = g_wth + (size_t)(w * HEAD + row) * N_EMBED + kc0 + q * 8;
        uint32_t d = smem_u32(sm + WOFF(ch % 3, w) + (row * WPH + q * 8) * 2);
        cp16(d, src);
    }
}

__global__ __launch_bounds__(256) void proj_kernel(const float* __restrict__ x)
{
    extern __shared__ char sm[];
    const int m0 = blockIdx.x * 128;
    const int t = threadIdx.x;
    const int warp = t >> 5, lane = t & 31;
    const int g = lane >> 2, tg = lane & 3;
    const int wm = warp >> 1, wn = warp & 1;
    const int l8 = lane & 7, mi = lane >> 3;

    const uint32_t smu = smem_u32(sm);
    const uint32_t aX = smu + XHOFF +
        ((wm * 32 + ((mi & 1) << 3) + l8) * WPH + ((mi >> 1) << 3)) * 2;
    const uint32_t bWl =
        ((uint32_t)(wn * 32 + ((mi >> 1) << 3) + l8) * WPH + ((mi & 1) << 3)) * 2;

    float4 acc[3][2][4] = {};

    // x prologue overlaps the wprep kernel (PDL): x does not depend on it
    proj_stage_x(sm, x, m0, 0, t); cp_commit();
    proj_stage_x(sm, x, m0, 1, t); cp_commit();

    cudaGridDependencySynchronize();   // wprep output (g_wth) now visible

    proj_stage_w(sm, 0, t);
    proj_stage_w(sm, 1, t);
    cp_commit();                       // groups outstanding: [x0][x1][w01]

    const int cr = t >> 1, cc = (t & 1) * 32;

    for (int ch = 0; ch < 16; ch++) {
        if (ch == 0 || ch == 15) cp_wait<0>(); else cp_wait<1>();
        __syncthreads();

        {
            const float* xf = reinterpret_cast<const float*>(sm + XF(ch & 1)) +
                              cr * XFP + cc;
            uint16_t* dst = reinterpret_cast<uint16_t*>(sm + XHOFF) + cr * WPH + cc;
            #pragma unroll
            for (int q = 0; q < 2; q++) {
                float4 f0 = *reinterpret_cast<const float4*>(xf + q * 16);
                float4 f1 = *reinterpret_cast<const float4*>(xf + q * 16 + 4);
                float4 f2 = *reinterpret_cast<const float4*>(xf + q * 16 + 8);
                float4 f3 = *reinterpret_cast<const float4*>(xf + q * 16 + 12);
                *reinterpret_cast<uint4*>(dst + q * 16) =
                    make_uint4(packhf(f0.x, f0.y), packhf(f0.z, f0.w),
                               packhf(f1.x, f1.y), packhf(f1.z, f1.w));
                *reinterpret_cast<uint4*>(dst + q * 16 + 8) =
                    make_uint4(packhf(f2.x, f2.y), packhf(f2.z, f2.w),
                               packhf(f3.x, f3.y), packhf(f3.z, f3.w));
            }
        }
        __syncthreads();

        if (ch + 2 < 16) {
            proj_stage_x(sm, x, m0, ch + 2, t);
            proj_stage_w(sm, ch + 2, t);
            cp_commit();
        }

        const int ring = ch % 3;
        #pragma unroll
        for (int kk = 0; kk < 4; kk++) {
            uint32_t a0[4], a1[4];
            ldsm4(a0[0], a0[1], a0[2], a0[3], aX + kk * 32);
            ldsm4(a1[0], a1[1], a1[2], a1[3], aX + 16 * WPH * 2 + kk * 32);
            #pragma unroll
            for (int w = 0; w < 3; w++) {
                const uint32_t bw = smu + WOFF(ring, w) + bWl;
                #pragma unroll
                for (int ntp = 0; ntp < 2; ntp++) {
                    uint32_t ba = bw + ntp * (16 * WPH * 2) + kk * 32;
                    uint32_t b0, b1, b2, b3;
                    ldsm4(b0, b1, b2, b3, ba);
                    mma16(acc[w][0][2*ntp],   a0[0], a0[1], a0[2], a0[3], b0, b1);
                    mma16(acc[w][0][2*ntp+1], a0[0], a0[1], a0[2], a0[3], b2, b3);
                    mma16(acc[w][1][2*ntp],   a1[0], a1[1], a1[2], a1[3], b0, b1);
                    mma16(acc[w][1][2*ntp+1], a1[0], a1[1], a1[2], a1[3], b2, b3);
                }
            }
        }
    }
    __syncthreads();

    #pragma unroll
    for (int mt = 0; mt < 2; mt++)
    #pragma unroll
    for (int nt = 0; nt < 4; nt++) {
        int m   = m0 + wm * 32 + mt * 16 + g;
        int col = wn * 32 + nt * 8 + 2 * tg;
        reinterpret_cast<uint32_t*>(g_qh)[((size_t)m * HEAD + col) >> 1] =
            packhf(acc[0][mt][nt].x * QSCALE, acc[0][mt][nt].y * QSCALE);
        reinterpret_cast<uint32_t*>(g_qh)[((size_t)(m + 8) * HEAD + col) >> 1] =
            packhf(acc[0][mt][nt].z * QSCALE, acc[0][mt][nt].w * QSCALE);
        reinterpret_cast<uint32_t*>(g_kh)[((size_t)m * HEAD + col) >> 1] =
            packhf(acc[1][mt][nt].x, acc[1][mt][nt].y);
        reinterpret_cast<uint32_t*>(g_kh)[((size_t)(m + 8) * HEAD + col) >> 1] =
            packhf(acc[1][mt][nt].z, acc[1][mt][nt].w);
    }

    float* sv = reinterpret_cast<float*>(sm);   // [128][68]
    #pragma unroll
    for (int mt = 0; mt < 2; mt++)
    #pragma unroll
    for (int nt = 0; nt < 4; nt++) {
        int r0 = wm * 32 + mt * 16 + g;
        int col = wn * 32 + nt * 8 + 2 * tg;
        sv[r0 * 68 + col] = acc[2][mt][nt].x; sv[r0 * 68 + col + 1] = acc[2][mt][nt].y;
        sv[(r0 + 8) * 68 + col] = acc[2][mt][nt].z; sv[(r0 + 8) * 68 + col + 1] = acc[2][mt][nt].w;
    }
    __syncthreads();
    {
        const int r = t >> 2, c32 = (t & 3) * 32;
        const int b = m0 >> 11;
        const int seq0 = m0 & 2047;
        #pragma unroll
        for (int gblk = 0; gblk < 4; gblk++) {
            uint32_t hp[4];
            #pragma unroll
            for (int i = 0; i < 4; i++)
                hp[i] = packhf(sv[(c32 + gblk * 8 + 2 * i) * 68 + r],
                               sv[(c32 + gblk * 8 + 2 * i + 1) * 68 + r]);
            size_t off = ((size_t)(b * HEAD + r)) * SEQ + seq0 + c32 + gblk * 8;
            *reinterpret_cast<uint4*>(&g_vth[off]) = make_uint4(hp[0], hp[1], hp[2], hp[3]);
        }
    }
}

// ---------------------------------------------------------------------------
// attn: split-KV depth 8, up to 4 slots per tile, n-way inline merge
// (R15-identical) + PDL grid-dependency sync at entry.
// ---------------------------------------------------------------------------
#define APE 72
#define APB (64 * APE * 2)
#define ATTN_SMEM (6 * APB)              // 55296 bytes

__constant__ uchar4 c_units[80] = {
    {31,0,8,0},{31,8,16,1},{31,16,24,2},{31,24,32,3},
    {30,0,8,0},{30,8,16,1},{30,16,24,2},
    {29,0,8,0},{29,8,16,1},{29,16,24,2},
    {28,0,8,0},{28,8,16,1},{28,16,24,2},
    {27,0,8,0},{27,8,16,1},{27,16,24,2},
    {26,0,8,0},{26,8,16,1},{26,16,24,2},
    {25,0,8,0},{25,8,16,1},{25,16,24,2},
    {24,0,8,0},{24,8,16,1},{24,16,24,2},
    {23,0,8,0},{23,8,16,1},{23,16,24,2},
    {22,0,8,0},{22,8,16,1},
    {21,0,8,0},{21,8,16,1},
    {20,0,8,0},{20,8,16,1},
    {19,0,8,0},{19,8,16,1},
    {18,0,8,0},{18,8,16,1},
    {17,0,8,0},{17,8,16,1},
    {16,0,8,0},{16,8,16,1},
    {15,0,8,0},{15,8,16,1},
    {14,0,8,0},{13,0,8,0},{12,0,8,0},{11,0,8,0},
    {10,0,8,0},{9,0,8,0},{8,0,8,0},{7,0,8,0},
    {30,24,31,3},{22,16,23,2},{14,8,15,1},{6,0,7,0},
    {29,24,30,3},{21,16,22,2},{13,8,14,1},{5,0,6,0},
    {28,24,29,3},{20,16,21,2},{12,8,13,1},{4,0,5,0},
    {27,24,28,3},{19,16,20,2},{11,8,12,1},{3,0,4,0},
    {26,24,27,3},{18,16,19,2},{10,8,11,1},{2,0,3,0},
    {25,24,26,3},{17,16,18,2},{9,8,10,1},{1,0,2,0},
    {24,24,25,3},{16,16,17,2},{8,8,9,1},{0,0,1,0}
};

__device__ __forceinline__ void stage_kv(char* sm,
    const uint16_t* __restrict__ gk, const uint16_t* __restrict__ gv,
    int j, int tid)
{
    char* smbuf = sm + 2 * (j % 3) * APB;
    #pragma unroll
    for (int i = 0; i < 4; i++) {
        int u = tid + i * 128;
        int r = u >> 3, c8 = (u & 7) * 8;
        uint32_t d = smem_u32(smbuf + (r * APE + c8) * 2);
        cp16(d,       gk + (size_t)(j * 64 + r) * HEAD + c8);
        cp16(d + APB, gv + (size_t)r * SEQ + j * 64 + c8);
    }
    cp_commit();
}

__global__ __launch_bounds__(128, 4) void attn_kernel(float* __restrict__ out)
{
    extern __shared__ char sm[];
    __shared__ int s_flag;

    cudaGridDependencySynchronize();   // proj outputs visible

    const uchar4 u = c_units[blockIdx.x];
    const int tile = u.x, c0 = u.y, c1 = u.z, slot = u.w;
    const int b = blockIdx.y;
    const int tid = threadIdx.x;
    const int warp = tid >> 5, lane = tid & 31;
    const int g = lane >> 2, tg = lane & 3;
    const int qr = warp * 16;
    const int l8 = lane & 7, mi = lane >> 3;

    const uint32_t smu = smem_u32(sm);
    const uint32_t bloc = ((((mi >> 1) << 3) + l8) * APE + ((mi & 1) << 3)) * 2;

    const int qslot = (c0 + 2) % 3;
    uint16_t* qh = reinterpret_cast<uint16_t*>(sm + 2 * qslot * APB);
    const uint32_t aQ = smu + 2 * qslot * APB +
        ((qr + ((mi & 1) << 3) + l8) * APE + ((mi >> 1) << 3)) * 2;

    const uint16_t* __restrict__ gqh = g_qh + (size_t)b * SEQ * HEAD;
    const uint16_t* __restrict__ gkh = g_kh + (size_t)b * SEQ * HEAD;
    const uint16_t* __restrict__ gvh = g_vth + (size_t)b * HEAD * SEQ;

    stage_kv(sm, gkh, gvh, c0, tid);
    if (c0 + 1 < c1) stage_kv(sm, gkh, gvh, c0 + 1, tid);

    #pragma unroll
    for (int i = 0; i < 4; i++) {
        int uu = tid + i * 128;
        int r = uu >> 3, c8 = (uu & 7) * 8;
        *reinterpret_cast<uint4*>(&qh[r * APE + c8]) =
            *reinterpret_cast<const uint4*>(&gqh[(size_t)(tile * 64 + r) * HEAD + c8]);
    }
    __syncthreads();

    uint32_t aq[4][4];
    #pragma unroll
    for (int kk = 0; kk < 4; kk++)
        ldsm4(aq[kk][0], aq[kk][1], aq[kk][2], aq[kk][3], aQ + kk * 32);

    float mx0 = -CUDART_INF_F, mx1 = -CUDART_INF_F;
    float l0 = 0.f, l1 = 0.f;
    float4 o[8] = {};

    for (int j = c0; j < c1; j++) {
        if (j == c1 - 1) cp_wait<0>(); else cp_wait<1>();
        __syncthreads();

        if (j + 2 < c1) stage_kv(sm, gkh, gvh, j + 2, tid);

        const uint32_t kb = smu + 2 * (j % 3) * APB + bloc;
        const uint32_t vb = kb + APB;

        float4 s[8] = {};
        #pragma unroll
        for (int kk = 0; kk < 4; kk++) {
            #pragma unroll
            for (int ntp = 0; ntp < 4; ntp++) {
                uint32_t ba = kb + ntp * (16 * APE * 2) + kk * 32;
                uint32_t bh0, bh1, bh2, bh3;
                ldsm4(bh0, bh1, bh2, bh3, ba);
                mma16(s[2*ntp],   aq[kk][0], aq[kk][1], aq[kk][2], aq[kk][3], bh0, bh1);
                mma16(s[2*ntp+1], aq[kk][0], aq[kk][1], aq[kk][2], aq[kk][3], bh2, bh3);
            }
        }

        if (j == tile) {
            const int rg0 = tile * 64 + qr + g;
            const int rg1 = rg0 + 8;
            #pragma unroll
            for (int nt = 0; nt < 8; nt++) {
                const int cg = j * 64 + nt * 8 + 2 * tg;
                if (cg     > rg0) s[nt].x = -CUDART_INF_F;
                if (cg + 1 > rg0) s[nt].y = -CUDART_INF_F;
                if (cg     > rg1) s[nt].z = -CUDART_INF_F;
                if (cg + 1 > rg1) s[nt].w = -CUDART_INF_F;
            }
        }

        float rm0 = -CUDART_INF_F, rm1 = -CUDART_INF_F;
        #pragma unroll
        for (int nt = 0; nt < 8; nt++) {
            rm0 = fmaxf(rm0, fmaxf(s[nt].x, s[nt].y));
            rm1 = fmaxf(rm1, fmaxf(s[nt].z, s[nt].w));
        }
        rm0 = fmaxf(rm0, __shfl_xor_sync(0xffffffffu, rm0, 1));
        rm0 = fmaxf(rm0, __shfl_xor_sync(0xffffffffu, rm0, 2));
        rm1 = fmaxf(rm1, __shfl_xor_sync(0xffffffffu, rm1, 1));
        rm1 = fmaxf(rm1, __shfl_xor_sync(0xffffffffu, rm1, 2));

        const bool renorm = __any_sync(0xffffffffu, (rm0 > mx0) | (rm1 > mx1));
        if (renorm) {
            const float nm0 = fmaxf(mx0, rm0);
            const float nm1 = fmaxf(mx1, rm1);
            const float a0 = ex2f(mx0 - nm0);
            const float a1 = ex2f(mx1 - nm1);
            l0 *= a0; l1 *= a1;
            mx0 = nm0; mx1 = nm1;
            #pragma unroll
            for (int nt = 0; nt < 8; nt++) {
                o[nt].x *= a0; o[nt].y *= a0;
                o[nt].z *= a1; o[nt].w *= a1;
            }
        }

        uint32_t pa[8], pb[8];
        float rs0 = 0.f, rs1 = 0.f;
        #pragma unroll
        for (int nt = 0; nt < 8; nt++) {
            float px = ex2f(s[nt].x - mx0);
            float py = ex2f(s[nt].y - mx0);
            float pz = ex2f(s[nt].z - mx1);
            float pw = ex2f(s[nt].w - mx1);
            rs0 += px + py;
            rs1 += pz + pw;
            pa[nt] = packhf(px, py);
            pb[nt] = packhf(pz, pw);
        }
        l0 += rs0;
        l1 += rs1;

        #pragma unroll
        for (int kk = 0; kk < 4; kk++) {
            uint32_t a0f = pa[2 * kk],     a1f = pb[2 * kk];
            uint32_t a2f = pa[2 * kk + 1], a3f = pb[2 * kk + 1];
            #pragma unroll
            for (int ntp = 0; ntp < 4; ntp++) {
                uint32_t ba = vb + ntp * (16 * APE * 2) + kk * 32;
                uint32_t vh0, vh1, vh2, vh3;
                ldsm4(vh0, vh1, vh2, vh3, ba);
                mma16(o[2*ntp],   a0f, a1f, a2f, a3f, vh0, vh1);
                mma16(o[2*ntp+1], a0f, a1f, a2f, a3f, vh2, vh3);
            }
        }
    }

    l0 += __shfl_xor_sync(0xffffffffu, l0, 1);
    l0 += __shfl_xor_sync(0xffffffffu, l0, 2);
    l1 += __shfl_xor_sync(0xffffffffu, l1, 1);
    l1 += __shfl_xor_sync(0xffffffffu, l1, 2);

    const int n = (tile >> 3) + 1;

    if (n == 1) {
        const float inv0 = __frcp_rn(l0);
        const float inv1 = __frcp_rn(l1);
        #pragma unroll
        for (int nt = 0; nt < 8; nt++) {
            int col = nt * 8 + 2 * tg;
            *reinterpret_cast<float2*>(
                &out[((size_t)b * SEQ + tile * 64 + qr + g    ) * HEAD + col]) =
                make_float2(o[nt].x * inv0, o[nt].y * inv0);
            *reinterpret_cast<float2*>(
                &out[((size_t)b * SEQ + tile * 64 + qr + g + 8) * HEAD + col]) =
                make_float2(o[nt].z * inv1, o[nt].w * inv1);
        }
        return;
    }

    const int tix  = b * 32 + tile;
    const int sidx = tix * 4 + slot;
    {
        float* po = g_po + (size_t)sidx * 64 * 64;
        #pragma unroll
        for (int nt = 0; nt < 8; nt++) {
            int col = nt * 8 + 2 * tg;
            *reinterpret_cast<float2*>(&po[(qr + g    ) * 64 + col]) = make_float2(o[nt].x, o[nt].y);
            *reinterpret_cast<float2*>(&po[(qr + g + 8) * 64 + col]) = make_float2(o[nt].z, o[nt].w);
        }
        if (tg == 0) {
            g_pm[sidx * 64 + qr + g    ] = mx0;
            g_pm[sidx * 64 + qr + g + 8] = mx1;
            g_pl[sidx * 64 + qr + g    ] = l0;
            g_pl[sidx * 64 + qr + g + 8] = l1;
        }
    }
    __threadfence();
    __syncthreads();
    if (tid == 0) {
        int old = atomicAdd(&g_cnt[tix], 1);
        s_flag = ((old % n) == (n - 1));
    }
    __syncthreads();
    if (!s_flag) return;
    __threadfence();

    const int r0i = qr + g, r1i = qr + g + 8;
    float pm0[4], pm1[4], pL0[4], pL1[4];
    float m0f = -CUDART_INF_F, m1f = -CUDART_INF_F;
    for (int sN = 0; sN < n; sN++) {
        pm0[sN] = g_pm[(tix * 4 + sN) * 64 + r0i];
        pm1[sN] = g_pm[(tix * 4 + sN) * 64 + r1i];
        pL0[sN] = g_pl[(tix * 4 + sN) * 64 + r0i];
        pL1[sN] = g_pl[(tix * 4 + sN) * 64 + r1i];
        m0f = fmaxf(m0f, pm0[sN]);
        m1f = fmaxf(m1f, pm1[sN]);
    }
    float w0[4], w1[4], L0 = 0.f, L1 = 0.f;
    for (int sN = 0; sN < n; sN++) {
        w0[sN] = ex2f(pm0[sN] - m0f);
        w1[sN] = ex2f(pm1[sN] - m1f);
        L0 += w0[sN] * pL0[sN];
        L1 += w1[sN] * pL1[sN];
    }
    const float inv0 = __frcp_rn(L0);
    const float inv1 = __frcp_rn(L1);
    for (int sN = 0; sN < n; sN++) { w0[sN] *= inv0; w1[sN] *= inv1; }

    #pragma unroll
    for (int nt = 0; nt < 8; nt++) {
        int col = nt * 8 + 2 * tg;
        float2 acc0 = make_float2(0.f, 0.f), acc1 = make_float2(0.f, 0.f);
        for (int sN = 0; sN < n; sN++) {
            const float* pp = g_po + (size_t)(tix * 4 + sN) * 64 * 64;
            float2 v0 = *reinterpret_cast<const float2*>(&pp[r0i * 64 + col]);
            float2 v1 = *reinterpret_cast<const float2*>(&pp[r1i * 64 + col]);
            acc0.x += v0.x * w0[sN]; acc0.y += v0.y * w0[sN];
            acc1.x += v1.x * w1[sN]; acc1.y += v1.y * w1[sN];
        }
        *reinterpret_cast<float2*>(
            &out[((size_t)b * SEQ + tile * 64 + r0i) * HEAD + col]) = acc0;
        *reinterpret_cast<float2*>(
            &out[((size_t)b * SEQ + tile * 64 + r1i) * HEAD + col]) = acc1;
    }
}

// ---------------------------------------------------------------------------
extern "C" void kernel_launch(void* const* d_in, const int* in_sizes, int n_in,
                              void* d_out, int out_size)
{
    const float* x  = (const float*)d_in[0];
    const float* Wq = (const float*)d_in[1];
    const float* Wk = (const float*)d_in[2];
    const float* Wv = (const float*)d_in[3];
    float* out = (float*)d_out;

    (void)in_sizes; (void)n_in; (void)out_size;

    cudaFuncSetAttribute(proj_kernel,
                         cudaFuncAttributeMaxDynamicSharedMemorySize, PROJ_SMEM);
    cudaFuncSetAttribute(attn_kernel,
                         cudaFuncAttributeMaxDynamicSharedMemorySize, ATTN_SMEM);

    wprep_kernel<<<dim3(64, 3), 256>>>(Wq, Wk, Wv);

    cudaLaunchAttribute pattr[1];
    pattr[0].id = cudaLaunchAttributeProgrammaticStreamSerialization;
    pattr[0].val.programmaticStreamSerializationAllowed = 1;

    cudaLaunchConfig_t cfgP = {};
    cfgP.gridDim = dim3(128);
    cfgP.blockDim = dim3(256);
    cfgP.dynamicSmemBytes = PROJ_SMEM;
    cfgP.attrs = pattr;
    cfgP.numAttrs = 1;
    cudaLaunchKernelEx(&cfgP, proj_kernel, x);

    cudaLaunchConfig_t cfgA = {};
    cfgA.gridDim = dim3(80, 8);
    cfgA.blockDim = dim3(128);
    cfgA.dynamicSmemBytes = ATTN_SMEM;
    cfgA.attrs = pattr;
    cfgA.numAttrs = 1;
    cudaLaunchKernelEx(&cfgA, attn_kernel, out);
}